// round 9
// baseline (speedup 1.0000x reference)
#include <cuda_runtime.h>
#include <cuda_bf16.h>

#define N_NODES 100000
#define N_EDGES 1600000
#define IN_CH 8
#define HID_CH 64
#define OUT_CH 2

// Scratch (allocation-free rule: __device__ globals).
__device__ __align__(32) float g_sum_x[N_NODES * IN_CH]; // layer-1 aggr, input space
__device__ float g_cnt[N_NODES];                          // in-degree
__device__ __align__(16) float g_p[N_NODES * OUT_CH];     // p = h @ W_l2^T
__device__ __align__(16) float g_self[N_NODES * OUT_CH];  // h @ W_r2^T + b_l2
__device__ __align__(16) float g_sum_p[N_NODES * OUT_CH]; // layer-2 aggr (2-dim)

// ---------------------------------------------------------------------------
// Zero accumulators (first kernel; no dependency)
// ---------------------------------------------------------------------------
__global__ void zero_kernel() {
    int total = N_NODES * IN_CH + N_NODES + N_NODES * OUT_CH;
    for (int i = blockIdx.x * blockDim.x + threadIdx.x; i < total;
         i += gridDim.x * blockDim.x) {
        if (i < N_NODES * IN_CH) {
            g_sum_x[i] = 0.0f;
        } else if (i < N_NODES * IN_CH + N_NODES) {
            g_cnt[i - N_NODES * IN_CH] = 0.0f;
        } else {
            g_sum_p[i - N_NODES * IN_CH - N_NODES] = 0.0f;
        }
    }
}

// ---------------------------------------------------------------------------
// Pass 1: 8 lanes per edge, one channel each. Input loads (ei, x) issue BEFORE
// the grid-dependency sync (they don't depend on zero_kernel); only the
// atomics into zeroed scratch wait.
// ---------------------------------------------------------------------------
__global__ void edge_pass1_kernel(const float* __restrict__ x,
                                  const int* __restrict__ ei, int E) {
    int idx = blockIdx.x * blockDim.x + threadIdx.x;
    int e  = idx >> 3;
    int ch = idx & 7;
    bool valid = (e < E);
    int src = 0, dst = 0;
    float v = 0.0f;
    if (valid) {
        src = ei[e];          // 8 lanes read same word -> broadcast
        dst = ei[E + e];
        v = x[src * IN_CH + ch];
    }
    cudaGridDependencySynchronize();   // wait for zero_kernel
    if (valid) {
        atomicAdd(&g_sum_x[dst * IN_CH + ch], v);
        if (ch == 0) atomicAdd(&g_cnt[dst], 1.0f);
    }
}

// ---------------------------------------------------------------------------
// Node kernel: fused  aggr/cnt -> lin1 -> ReLU -> p = h@Wl2^T, self = h@Wr2^T+b2
// Weight/x staging happens before the sync (inputs); g_sum_x/g_cnt reads after.
// ---------------------------------------------------------------------------
__global__ void node_kernel(const float* __restrict__ x,
                            const float* __restrict__ W_l1,  // [64,8]
                            const float* __restrict__ b_l1,  // [64]
                            const float* __restrict__ W_r1,  // [64,8]
                            const float* __restrict__ W_l2,  // [2,64]
                            const float* __restrict__ b_l2,  // [2]
                            const float* __restrict__ W_r2,  // [2,64]
                            int N) {
    __shared__ float sWl1[HID_CH * IN_CH];
    __shared__ float sWr1[HID_CH * IN_CH];
    __shared__ float sWl2[OUT_CH * HID_CH];
    __shared__ float sWr2[OUT_CH * HID_CH];
    __shared__ float sb1[HID_CH];
    __shared__ float sb2[OUT_CH];

    for (int i = threadIdx.x; i < HID_CH * IN_CH; i += blockDim.x) {
        sWl1[i] = W_l1[i];
        sWr1[i] = W_r1[i];
    }
    for (int i = threadIdx.x; i < OUT_CH * HID_CH; i += blockDim.x) {
        sWl2[i] = W_l2[i];
        sWr2[i] = W_r2[i];
    }
    if (threadIdx.x < HID_CH) sb1[threadIdx.x] = b_l1[threadIdx.x];
    if (threadIdx.x < OUT_CH) sb2[threadIdx.x] = b_l2[threadIdx.x];

    int i = blockIdx.x * blockDim.x + threadIdx.x;

    float xi[IN_CH];
    if (i < N) {
        const float4* x4 = (const float4*)&x[i * IN_CH];
        float4 xa = x4[0], xb = x4[1];
        xi[0] = xa.x; xi[1] = xa.y; xi[2] = xa.z; xi[3] = xa.w;
        xi[4] = xb.x; xi[5] = xb.y; xi[6] = xb.z; xi[7] = xb.w;
    }

    cudaGridDependencySynchronize();   // wait for edge_pass1
    __syncthreads();

    if (i >= N) return;

    float cnt = g_cnt[i];
    float inv = 1.0f / fmaxf(cnt, 1.0f);

    float aggr[IN_CH];
    const float4* sx4 = (const float4*)&g_sum_x[i * IN_CH];
    float4 sa = sx4[0], sb = sx4[1];
    aggr[0] = sa.x * inv; aggr[1] = sa.y * inv; aggr[2] = sa.z * inv; aggr[3] = sa.w * inv;
    aggr[4] = sb.x * inv; aggr[5] = sb.y * inv; aggr[6] = sb.z * inv; aggr[7] = sb.w * inv;

    float p0 = 0.0f, p1 = 0.0f, s0 = 0.0f, s1 = 0.0f;
#pragma unroll
    for (int j = 0; j < HID_CH; j++) {
        float t = sb1[j];
#pragma unroll
        for (int k = 0; k < IN_CH; k++) {
            t = fmaf(aggr[k], sWl1[j * IN_CH + k], t);
            t = fmaf(xi[k],   sWr1[j * IN_CH + k], t);
        }
        float h = fmaxf(t, 0.0f);   // ReLU (dropout is identity in eval)
        p0 = fmaf(h, sWl2[0 * HID_CH + j], p0);
        p1 = fmaf(h, sWl2[1 * HID_CH + j], p1);
        s0 = fmaf(h, sWr2[0 * HID_CH + j], s0);
        s1 = fmaf(h, sWr2[1 * HID_CH + j], s1);
    }

    g_p[i * 2 + 0] = p0;
    g_p[i * 2 + 1] = p1;
    g_self[i * 2 + 0] = s0 + sb2[0];
    g_self[i * 2 + 1] = s1 + sb2[1];
}

// ---------------------------------------------------------------------------
// Pass 2: 2 lanes per edge. ei loads before sync; g_p gather + atomics after.
// ---------------------------------------------------------------------------
__global__ void edge_pass2_kernel(const int* __restrict__ ei, int E) {
    int idx = blockIdx.x * blockDim.x + threadIdx.x;
    int e  = idx >> 1;
    int ch = idx & 1;
    bool valid = (e < E);
    int src = 0, dst = 0;
    if (valid) {
        src = ei[e];
        dst = ei[E + e];
    }
    cudaGridDependencySynchronize();   // wait for node_kernel
    if (valid) {
        float v = g_p[src * 2 + ch];
        atomicAdd(&g_sum_p[dst * 2 + ch], v);
    }
}

// ---------------------------------------------------------------------------
// Finalize: out = sum_p / max(cnt,1) + self
// ---------------------------------------------------------------------------
__global__ void finalize_kernel(float* __restrict__ out, int N) {
    int i = blockIdx.x * blockDim.x + threadIdx.x;
    cudaGridDependencySynchronize();   // wait for edge_pass2
    if (i >= N) return;
    float inv = 1.0f / fmaxf(g_cnt[i], 1.0f);
    float2 sp = *(const float2*)&g_sum_p[i * 2];
    float2 se = *(const float2*)&g_self[i * 2];
    float2 o;
    o.x = sp.x * inv + se.x;
    o.y = sp.y * inv + se.y;
    *(float2*)&out[i * 2] = o;
}

// ---------------------------------------------------------------------------
// Host: launch chain with programmatic dependent launch (overlap launch
// latency + input prefetch with predecessor's tail).
// ---------------------------------------------------------------------------
template <typename... Args>
static void launch_pdl(void (*kern)(Args...), dim3 grid, dim3 block,
                       Args... args) {
    cudaLaunchConfig_t cfg = {};
    cfg.gridDim = grid;
    cfg.blockDim = block;
    cfg.dynamicSmemBytes = 0;
    cfg.stream = 0;
    cudaLaunchAttribute attr;
    attr.id = cudaLaunchAttributeProgrammaticStreamSerialization;
    attr.val.programmaticStreamSerializationAllowed = 1;
    cfg.attrs = &attr;
    cfg.numAttrs = 1;
    cudaLaunchKernelEx(&cfg, kern, args...);
}

extern "C" void kernel_launch(void* const* d_in, const int* in_sizes, int n_in,
                              void* d_out, int out_size) {
    const float* x    = (const float*)d_in[0];
    const int*   ei   = (const int*)d_in[1];
    const float* W_l1 = (const float*)d_in[2];
    const float* b_l1 = (const float*)d_in[3];
    const float* W_r1 = (const float*)d_in[4];
    const float* W_l2 = (const float*)d_in[5];
    const float* b_l2 = (const float*)d_in[6];
    const float* W_r2 = (const float*)d_in[7];

    int E = in_sizes[1] / 2;
    int N = in_sizes[0] / IN_CH;

    zero_kernel<<<1024, 256>>>();
    launch_pdl(edge_pass1_kernel, dim3((8 * E + 255) / 256), dim3(256), x, ei, E);
    launch_pdl(node_kernel, dim3((N + 255) / 256), dim3(256),
               x, W_l1, b_l1, W_r1, W_l2, b_l2, W_r2, N);
    launch_pdl(edge_pass2_kernel, dim3((2 * E + 255) / 256), dim3(256), ei, E);
    launch_pdl(finalize_kernel, dim3((N + 255) / 256), dim3(256), (float*)d_out, N);
}

// round 10
// speedup vs baseline: 1.1009x; 1.1009x over previous
#include <cuda_runtime.h>
#include <cuda_bf16.h>

#define N_NODES 100000
#define N_EDGES 1600000
#define IN_CH 8
#define HID_CH 64
#define OUT_CH 2

// Scratch (allocation-free rule: __device__ globals).
__device__ __align__(32) float g_sum_x[N_NODES * IN_CH]; // layer-1 aggr, input space
__device__ float g_cnt[N_NODES];                          // in-degree
__device__ __align__(16) float g_p[N_NODES * OUT_CH];     // p = h @ W_l2^T
__device__ __align__(16) float g_self[N_NODES * OUT_CH];  // h @ W_r2^T + b_l2
__device__ __align__(16) float g_sum_p[N_NODES * OUT_CH]; // layer-2 aggr (2-dim)

// ---------------------------------------------------------------------------
// Zero accumulators (must run every call: deterministic, no caching)
// ---------------------------------------------------------------------------
__global__ void zero_kernel() {
    int total = N_NODES * IN_CH + N_NODES + N_NODES * OUT_CH;
    for (int i = blockIdx.x * blockDim.x + threadIdx.x; i < total;
         i += gridDim.x * blockDim.x) {
        if (i < N_NODES * IN_CH) {
            g_sum_x[i] = 0.0f;
        } else if (i < N_NODES * IN_CH + N_NODES) {
            g_cnt[i - N_NODES * IN_CH] = 0.0f;
        } else {
            g_sum_p[i - N_NODES * IN_CH - N_NODES] = 0.0f;
        }
    }
}

// ---------------------------------------------------------------------------
// Pass 1: 8 lanes per edge (one channel each, sector-coalesced REDs),
// 2 edges per thread with front-batched independent loads for MLP.
// ---------------------------------------------------------------------------
__global__ void edge_pass1_kernel(const float* __restrict__ x,
                                  const int* __restrict__ ei, int E, int EH) {
    int idx = blockIdx.x * blockDim.x + threadIdx.x;
    int t  = idx >> 3;
    int ch = idx & 7;
    int e1 = t;
    int e2 = t + EH;
    bool v1 = (e1 < E);
    bool v2 = (e2 < E);

    // Batch index loads (independent)
    int src1 = 0, dst1 = 0, src2 = 0, dst2 = 0;
    if (v1) { src1 = ei[e1]; dst1 = ei[E + e1]; }
    if (v2) { src2 = ei[e2]; dst2 = ei[E + e2]; }

    // Batch gathers (independent)
    float x1 = 0.0f, x2 = 0.0f;
    if (v1) x1 = x[src1 * IN_CH + ch];
    if (v2) x2 = x[src2 * IN_CH + ch];

    // Scatter
    if (v1) {
        atomicAdd(&g_sum_x[dst1 * IN_CH + ch], x1);
        if (ch == 0) atomicAdd(&g_cnt[dst1], 1.0f);
    }
    if (v2) {
        atomicAdd(&g_sum_x[dst2 * IN_CH + ch], x2);
        if (ch == 0) atomicAdd(&g_cnt[dst2], 1.0f);
    }
}

// ---------------------------------------------------------------------------
// Node kernel: fused  aggr/cnt -> lin1 -> ReLU -> p = h@Wl2^T, self = h@Wr2^T+b2
// h (64-dim) stays in registers; weights staged in shared memory (broadcast).
// ---------------------------------------------------------------------------
__global__ void node_kernel(const float* __restrict__ x,
                            const float* __restrict__ W_l1,  // [64,8]
                            const float* __restrict__ b_l1,  // [64]
                            const float* __restrict__ W_r1,  // [64,8]
                            const float* __restrict__ W_l2,  // [2,64]
                            const float* __restrict__ b_l2,  // [2]
                            const float* __restrict__ W_r2,  // [2,64]
                            int N) {
    __shared__ float sWl1[HID_CH * IN_CH];
    __shared__ float sWr1[HID_CH * IN_CH];
    __shared__ float sWl2[OUT_CH * HID_CH];
    __shared__ float sWr2[OUT_CH * HID_CH];
    __shared__ float sb1[HID_CH];
    __shared__ float sb2[OUT_CH];

    for (int i = threadIdx.x; i < HID_CH * IN_CH; i += blockDim.x) {
        sWl1[i] = W_l1[i];
        sWr1[i] = W_r1[i];
    }
    for (int i = threadIdx.x; i < OUT_CH * HID_CH; i += blockDim.x) {
        sWl2[i] = W_l2[i];
        sWr2[i] = W_r2[i];
    }
    if (threadIdx.x < HID_CH) sb1[threadIdx.x] = b_l1[threadIdx.x];
    if (threadIdx.x < OUT_CH) sb2[threadIdx.x] = b_l2[threadIdx.x];
    __syncthreads();

    int i = blockIdx.x * blockDim.x + threadIdx.x;
    if (i >= N) return;

    float cnt = g_cnt[i];
    float inv = 1.0f / fmaxf(cnt, 1.0f);

    float aggr[IN_CH], xi[IN_CH];
    const float4* sx4 = (const float4*)&g_sum_x[i * IN_CH];
    float4 sa = sx4[0], sb = sx4[1];
    aggr[0] = sa.x * inv; aggr[1] = sa.y * inv; aggr[2] = sa.z * inv; aggr[3] = sa.w * inv;
    aggr[4] = sb.x * inv; aggr[5] = sb.y * inv; aggr[6] = sb.z * inv; aggr[7] = sb.w * inv;

    const float4* x4 = (const float4*)&x[i * IN_CH];
    float4 xa = x4[0], xb = x4[1];
    xi[0] = xa.x; xi[1] = xa.y; xi[2] = xa.z; xi[3] = xa.w;
    xi[4] = xb.x; xi[5] = xb.y; xi[6] = xb.z; xi[7] = xb.w;

    float p0 = 0.0f, p1 = 0.0f, s0 = 0.0f, s1 = 0.0f;
#pragma unroll
    for (int j = 0; j < HID_CH; j++) {
        float t = sb1[j];
#pragma unroll
        for (int k = 0; k < IN_CH; k++) {
            t = fmaf(aggr[k], sWl1[j * IN_CH + k], t);
            t = fmaf(xi[k],   sWr1[j * IN_CH + k], t);
        }
        float h = fmaxf(t, 0.0f);   // ReLU (dropout is identity in eval)
        p0 = fmaf(h, sWl2[0 * HID_CH + j], p0);
        p1 = fmaf(h, sWl2[1 * HID_CH + j], p1);
        s0 = fmaf(h, sWr2[0 * HID_CH + j], s0);
        s1 = fmaf(h, sWr2[1 * HID_CH + j], s1);
    }

    g_p[i * 2 + 0] = p0;
    g_p[i * 2 + 1] = p1;
    g_self[i * 2 + 0] = s0 + sb2[0];
    g_self[i * 2 + 1] = s1 + sb2[1];
}

// ---------------------------------------------------------------------------
// Pass 2: 2 lanes per edge (sector-coalesced), 4 edges per thread with
// front-batched loads for MLP.
// ---------------------------------------------------------------------------
__global__ void edge_pass2_kernel(const int* __restrict__ ei, int E, int EQ) {
    int idx = blockIdx.x * blockDim.x + threadIdx.x;
    int t  = idx >> 1;
    int ch = idx & 1;

    int e[4];
    bool v[4];
    int src[4], dst[4];
    float val[4];
#pragma unroll
    for (int k = 0; k < 4; k++) {
        e[k] = t + k * EQ;
        v[k] = (e[k] < E);
        src[k] = 0; dst[k] = 0;
    }
#pragma unroll
    for (int k = 0; k < 4; k++)
        if (v[k]) { src[k] = ei[e[k]]; dst[k] = ei[E + e[k]]; }
#pragma unroll
    for (int k = 0; k < 4; k++) {
        val[k] = 0.0f;
        if (v[k]) val[k] = g_p[src[k] * 2 + ch];
    }
#pragma unroll
    for (int k = 0; k < 4; k++)
        if (v[k]) atomicAdd(&g_sum_p[dst[k] * 2 + ch], val[k]);
}

// ---------------------------------------------------------------------------
// Finalize: out = sum_p / max(cnt,1) + self
// ---------------------------------------------------------------------------
__global__ void finalize_kernel(float* __restrict__ out, int N) {
    int i = blockIdx.x * blockDim.x + threadIdx.x;
    if (i >= N) return;
    float inv = 1.0f / fmaxf(g_cnt[i], 1.0f);
    float2 sp = *(const float2*)&g_sum_p[i * 2];
    float2 se = *(const float2*)&g_self[i * 2];
    float2 o;
    o.x = sp.x * inv + se.x;
    o.y = sp.y * inv + se.y;
    *(float2*)&out[i * 2] = o;
}

extern "C" void kernel_launch(void* const* d_in, const int* in_sizes, int n_in,
                              void* d_out, int out_size) {
    const float* x    = (const float*)d_in[0];
    const int*   ei   = (const int*)d_in[1];
    const float* W_l1 = (const float*)d_in[2];
    const float* b_l1 = (const float*)d_in[3];
    const float* W_r1 = (const float*)d_in[4];
    const float* W_l2 = (const float*)d_in[5];
    const float* b_l2 = (const float*)d_in[6];
    const float* W_r2 = (const float*)d_in[7];

    int E = in_sizes[1] / 2;
    int N = in_sizes[0] / IN_CH;
    int EH = (E + 1) / 2;   // pass-1: 2 edges per thread
    int EQ = (E + 3) / 4;   // pass-2: 4 edges per thread

    zero_kernel<<<1024, 256>>>();
    edge_pass1_kernel<<<(8 * EH + 255) / 256, 256>>>(x, ei, E, EH);
    node_kernel<<<(N + 255) / 256, 256>>>(x, W_l1, b_l1, W_r1, W_l2, b_l2, W_r2, N);
    edge_pass2_kernel<<<(2 * EQ + 255) / 256, 256>>>(ei, E, EQ);
    finalize_kernel<<<(N + 255) / 256, 256>>>((float*)d_out, N);
}